// round 6
// baseline (speedup 1.0000x reference)
#include <cuda_runtime.h>
#include <math.h>

// ---------------- device scratch ----------------
__device__ float g_blur[4 * 224 * 224 * 256];   // blurred feats, layout [b][y][x][c]
__device__ float g_wp[81 * 256];                // weights repacked [k*9+tap][c]
__device__ int   g_mask_mode;                   // 0=uint8, 1=int32, 2=float32

// ---------------- mask dtype detection ----------------
__global__ void detect_mask_kernel(const unsigned* __restrict__ m) {
    int lane = threadIdx.x;  // 32 threads
    int fcount = 0, zocount = 0;
#pragma unroll
    for (int i = 0; i < 8; i++) {
        unsigned w = m[lane * 8 + i];
        if (w == 0x3f800000u) fcount++;
        if (w <= 1u) zocount++;
    }
#pragma unroll
    for (int o = 16; o; o >>= 1) {
        fcount  += __shfl_xor_sync(0xffffffffu, fcount, o);
        zocount += __shfl_xor_sync(0xffffffffu, zocount, o);
    }
    if (lane == 0) g_mask_mode = (fcount > 0) ? 2 : ((zocount == 256) ? 1 : 0);
}

// ---------------- weight repack: (9,256,3,3) -> [k*9+tap][c] ----------------
__global__ void repack_kernel(const float* __restrict__ ak) {
    int idx = blockIdx.x * 256 + threadIdx.x;  // 81 blocks * 256 = 20736
    int c  = idx & 255;
    int kt = idx >> 8;           // k*9 + tap, 0..80
    int k = kt / 9, tap = kt - k * 9;
    g_wp[idx] = ak[(k * 256 + c) * 9 + tap];
}

// ---------------- separable 5x5 gaussian blur (round-3 proven config) ------
// CTA: 32 channels x 16y x 32x tile, 512 threads, vertical-first rolling pass.
#define BLUR_SMEM (32 * 593 * 4)

__global__ void __launch_bounds__(512, 2) blur_kernel(const float* __restrict__ hr) {
    extern __shared__ float s_v[];

    const float C = -1.4142135623730951f;
    float tb[5]; float s = 0.f;
#pragma unroll
    for (int j = 0; j < 5; j++) { float d = (float)(j - 2); tb[j] = expf(d * d * C); s += tb[j]; }
#pragma unroll
    for (int j = 0; j < 5; j++) tb[j] = tb[j] / s;

    int b = blockIdx.z, cb = blockIdx.y;
    int tx = blockIdx.x % 7, ty = blockIdx.x / 7;
    int x0 = tx * 32, y0 = ty * 16;
    int t = threadIdx.x;

    // phase 1: vertical blur, rolling window per column. 1152 columns (32ch x 36x)
    for (int j = t; j < 1152; j += 512) {
        int ch = j / 36, lx = j - ch * 36;
        int ix = x0 - 2 + lx;
        bool vx = (ix >= 0 && ix < 224);
        const float* base = hr + ((long)(b * 256 + cb * 32 + ch) * 224) * 224 + ix;
        float w0 = 0.f, w1 = 0.f, w2 = 0.f, w3 = 0.f, w4 = 0.f;
        float* ov = s_v + ch * 593 + lx;
#pragma unroll
        for (int yy = 0; yy < 20; yy++) {
            int iy = y0 - 2 + yy;
            float v = (vx && iy >= 0 && iy < 224) ? base[iy * 224] : 0.f;
            w0 = w1; w1 = w2; w2 = w3; w3 = w4; w4 = v;
            if (yy >= 4) {
                float o = w0*tb[0] + w1*tb[1] + w2*tb[2] + w3*tb[3] + w4*tb[4];
                ov[(yy - 4) * 37] = o;
            }
        }
    }
    __syncthreads();

    // phase 2: horizontal blur + transposed store (lane = channel -> 128B stores)
    {
        int ch = t & 31, yr = t >> 5;   // yr 0..15
        const float* vp = s_v + ch * 593 + yr * 37;
        float* ob = g_blur + ((long)(b * 224 + y0 + yr) * 224 + x0) * 256 + cb * 32 + ch;
        float a0 = vp[0], a1 = vp[1], a2 = vp[2], a3 = vp[3];
#pragma unroll
        for (int x = 0; x < 32; x++) {
            float a4 = vp[x + 4];
            float o = a0*tb[0] + a1*tb[1] + a2*tb[2] + a3*tb[3] + a4*tb[4];
            ob[x * 256] = o;
            a0 = a1; a1 = a2; a2 = a3; a3 = a4;
        }
    }
}

// ---------------- fused logits + softmax + einsum v4 ----------------
// CTA: 2x8 output tile, 384 threads.
// s_blur: 5x17 region, parity-split rows, 85 rows x 260 floats:
//   even rix: row = riy*9 + rix/2      (45 rows)
//   odd  rix: row = 45 + riy*8 + rix/2 (40 rows)
// phase B thread tile: (cs = t&31 [8ch slice: c4=cs and cs+32],
//                       kg = (t>>5)%3 [3 k's], pg = t/96 [4 px: py=pg>>1, xh=pg&1])
//   acc[3][4] = 12 regs; per tap: 8 LDS.128 (v) + 6 LDG.128 (w) + 96 FMA.
//   Warp = (pg,kg); butterfly over 32 lanes reduces all 256 channels ->
//   lane 0 writes logits directly (no combine phase).
// smem floats: s_blur 22100 | s_logit 144 | s_attn 144
#define FUSED_SMEM ((22100 + 144 + 144) * 4)

__global__ void __launch_bounds__(384) fused_kernel(
    const void* __restrict__ maskp,
    const float* __restrict__ kbias,
    const float* __restrict__ lbias,
    float* __restrict__ out)
{
    extern __shared__ float sm[];
    float* s_blur  = sm;             // 22100
    float* s_logit = sm + 22100;     // 144
    float* s_attn  = sm + 22244;     // 144

    int t = threadIdx.x;
    int b = blockIdx.z;
    int x0o = blockIdx.x * 8, y0o = blockIdx.y * 2;
    int rx0 = 2 * x0o - 1, ry0 = 2 * y0o - 1;

    // ---- load 5x17 blurred region (85 rows x 256ch), 6 row-streams ----
    {
        int c4 = t & 63, rr = t >> 6;   // rr 0..5
        const float* gb = g_blur + (long)b * 224 * 224 * 256 + c4 * 4;
        for (int row = rr; row < 85; row += 6) {
            int riy, rix;
            if (row < 45) { riy = row / 9;  rix = 2 * (row - riy * 9); }
            else { int q = row - 45; riy = q >> 3; rix = 2 * (q & 7) + 1; }
            int iy = ry0 + riy, ix = rx0 + rix;
            float4 v = make_float4(0.f, 0.f, 0.f, 0.f);
            if (iy >= 0 && iy < 224 && ix >= 0 && ix < 224)
                v = *(const float4*)(gb + ((long)iy * 224 + ix) * 256);
            *(float4*)(s_blur + row * 260 + c4 * 4) = v;
        }
    }
    __syncthreads();

    // ---- phase B: logits, thread tile 4px x 3k x 8ch ----
    {
        int cs = t & 31;
        int kg = (t >> 5) % 3;
        int pg = t / 96;                 // 0..3
        int py = pg >> 1, xh = pg & 1;
        const float4* sb4 = (const float4*)s_blur;   // row stride 65 float4
        const float4* wp4 = (const float4*)g_wp;     // kt stride 64 float4

        float acc[3][4];
#pragma unroll
        for (int k = 0; k < 3; k++)
#pragma unroll
            for (int i = 0; i < 4; i++) acc[k][i] = 0.f;

#pragma unroll
        for (int dy = 0; dy < 3; dy++) {
            int riy = 2 * py + dy;
            int re = riy * 9 + 4 * xh;        // even-rix base (dx=0)
            int ro = 45 + riy * 8 + 4 * xh;   // odd-rix base
#pragma unroll
            for (int dx = 0; dx < 3; dx++) {
                int rbase = (dx == 1) ? ro : (re + (dx >> 1));
                int tap = dy * 3 + dx;
                float4 vl[4], vh[4];
#pragma unroll
                for (int i = 0; i < 4; i++) {
                    vl[i] = sb4[(rbase + i) * 65 + cs];
                    vh[i] = sb4[(rbase + i) * 65 + cs + 32];
                }
#pragma unroll
                for (int k = 0; k < 3; k++) {
                    int kt = (kg * 3 + k) * 9 + tap;
                    float4 wl = __ldg(&wp4[kt * 64 + cs]);
                    float4 wh = __ldg(&wp4[kt * 64 + cs + 32]);
#pragma unroll
                    for (int i = 0; i < 4; i++) {
                        float a = acc[k][i];
                        a = fmaf(vl[i].x, wl.x, a);
                        a = fmaf(vl[i].y, wl.y, a);
                        a = fmaf(vl[i].z, wl.z, a);
                        a = fmaf(vl[i].w, wl.w, a);
                        a = fmaf(vh[i].x, wh.x, a);
                        a = fmaf(vh[i].y, wh.y, a);
                        a = fmaf(vh[i].z, wh.z, a);
                        a = fmaf(vh[i].w, wh.w, a);
                        acc[k][i] = a;
                    }
                }
            }
        }

        // butterfly over 32 channel-slices = full 256-channel reduction
#pragma unroll
        for (int o = 16; o; o >>= 1)
#pragma unroll
            for (int k = 0; k < 3; k++)
#pragma unroll
                for (int i = 0; i < 4; i++)
                    acc[k][i] += __shfl_xor_sync(0xffffffffu, acc[k][i], o);

        if (cs == 0) {
#pragma unroll
            for (int k = 0; k < 3; k++)
#pragma unroll
                for (int i = 0; i < 4; i++) {
                    int p = py * 8 + 4 * xh + i;
                    s_logit[p * 9 + kg * 3 + k] = acc[k][i];
                }
        }
    }
    __syncthreads();

    // ---- softmax over 9 with kbias + keep_mask + logit_bias ----
    if (t < 16) {
        int p = t;
        int oy = y0o + (p >> 3), ox = x0o + (p & 7);
        int mm = g_mask_mode;
        float lg[9];
#pragma unroll
        for (int k = 0; k < 9; k++) {
            long midx = ((long)(b * 9 + k) * 112 + oy) * 112 + ox;
            bool keep;
            if (mm == 0)      keep = ((const unsigned char*)maskp)[midx] != 0;
            else if (mm == 1) keep = ((const int*)maskp)[midx] != 0;
            else              keep = ((const float*)maskp)[midx] != 0.f;
            lg[k] = (keep ? (s_logit[p * 9 + k] + kbias[k]) : 0.f) + lbias[k];
        }
        float mx = lg[0];
#pragma unroll
        for (int k = 1; k < 9; k++) mx = fmaxf(mx, lg[k]);
        float e[9]; float ssum = 0.f;
#pragma unroll
        for (int k = 0; k < 9; k++) { e[k] = expf(lg[k] - mx); ssum += e[k]; }
        float invs = 1.0f / ssum;
#pragma unroll
        for (int k = 0; k < 9; k++) s_attn[p * 9 + k] = e[k] * invs;
    }
    __syncthreads();

    // ---- einsum: thread = c (first 256 threads), both rows, 16 outputs ----
    if (t < 256) {
        int c = t;
#pragma unroll
        for (int r = 0; r < 2; r++) {
            float ox[8];
#pragma unroll
            for (int x = 0; x < 8; x++) ox[x] = 0.f;
#pragma unroll
            for (int dy = 0; dy < 3; dy++) {
                int riy = 2 * r + dy;
#pragma unroll
                for (int dx = 0; dx < 3; dx++) {
                    int k = dy * 3 + dx;
#pragma unroll
                    for (int x = 0; x < 8; x++) {
                        int rix = 2 * x + dx;
                        int row = (rix & 1) ? (45 + riy * 8 + (rix >> 1))
                                            : (riy * 9 + (rix >> 1));
                        float v = s_blur[row * 260 + c];
                        float a = s_attn[(r * 8 + x) * 9 + k];
                        ox[x] = fmaf(v, a, ox[x]);
                    }
                }
            }
            float* ob = out + ((long)(b * 256 + c) * 112 + y0o + r) * 112 + x0o;
            *(float4*)(ob)     = make_float4(ox[0], ox[1], ox[2], ox[3]);
            *(float4*)(ob + 4) = make_float4(ox[4], ox[5], ox[6], ox[7]);
        }
    }
}

// ---------------- launch ----------------
extern "C" void kernel_launch(void* const* d_in, const int* in_sizes, int n_in,
                              void* d_out, int out_size) {
    const float* hr  = (const float*)d_in[0];
    const float* ak  = (const float*)d_in[1];
    const float* kb  = (const float*)d_in[2];
    const float* lb  = (const float*)d_in[3];
    const void*  msk = d_in[4];
    float* out = (float*)d_out;
    (void)in_sizes; (void)n_in; (void)out_size;

    cudaFuncSetAttribute(blur_kernel,  cudaFuncAttributeMaxDynamicSharedMemorySize, BLUR_SMEM);
    cudaFuncSetAttribute(fused_kernel, cudaFuncAttributeMaxDynamicSharedMemorySize, FUSED_SMEM);

    detect_mask_kernel<<<1, 32>>>((const unsigned*)msk);
    repack_kernel<<<81, 256>>>(ak);
    blur_kernel<<<dim3(98, 8, 4), 512, BLUR_SMEM>>>(hr);
    fused_kernel<<<dim3(14, 56, 4), 384, FUSED_SMEM>>>(msk, kb, lb, out);
}

// round 7
// speedup vs baseline: 1.0169x; 1.0169x over previous
#include <cuda_runtime.h>
#include <math.h>

// ---------------- device scratch ----------------
__device__ float g_blur[4 * 224 * 224 * 256];   // blurred feats, layout [b][y][x][c]
__device__ float g_wp[81 * 256];                // weights repacked [k*9+tap][c]
__device__ int   g_mask_mode;                   // 0=uint8, 1=int32, 2=float32

// ---------------- mask dtype detection ----------------
__global__ void detect_mask_kernel(const unsigned* __restrict__ m) {
    int lane = threadIdx.x;  // 32 threads
    int fcount = 0, zocount = 0;
#pragma unroll
    for (int i = 0; i < 8; i++) {
        unsigned w = m[lane * 8 + i];
        if (w == 0x3f800000u) fcount++;
        if (w <= 1u) zocount++;
    }
#pragma unroll
    for (int o = 16; o; o >>= 1) {
        fcount  += __shfl_xor_sync(0xffffffffu, fcount, o);
        zocount += __shfl_xor_sync(0xffffffffu, zocount, o);
    }
    if (lane == 0) g_mask_mode = (fcount > 0) ? 2 : ((zocount == 256) ? 1 : 0);
}

// ---------------- weight repack: (9,256,3,3) -> [k*9+tap][c] ----------------
__global__ void repack_kernel(const float* __restrict__ ak) {
    int idx = blockIdx.x * 256 + threadIdx.x;  // 81 blocks * 256 = 20736
    int c  = idx & 255;
    int kt = idx >> 8;           // k*9 + tap, 0..80
    int k = kt / 9, tap = kt - k * 9;
    g_wp[idx] = ak[(k * 256 + c) * 9 + tap];
}

// ---------------- separable 5x5 gaussian blur (round-3 proven config) ------
// CTA: 32 channels x 16y x 32x tile, 512 threads, vertical-first rolling pass.
#define BLUR_SMEM (32 * 593 * 4)

__global__ void __launch_bounds__(512, 2) blur_kernel(const float* __restrict__ hr) {
    extern __shared__ float s_v[];

    const float C = -1.4142135623730951f;
    float tb[5]; float s = 0.f;
#pragma unroll
    for (int j = 0; j < 5; j++) { float d = (float)(j - 2); tb[j] = expf(d * d * C); s += tb[j]; }
#pragma unroll
    for (int j = 0; j < 5; j++) tb[j] = tb[j] / s;

    int b = blockIdx.z, cb = blockIdx.y;
    int tx = blockIdx.x % 7, ty = blockIdx.x / 7;
    int x0 = tx * 32, y0 = ty * 16;
    int t = threadIdx.x;

    // phase 1: vertical blur, rolling window per column. 1152 columns (32ch x 36x)
    for (int j = t; j < 1152; j += 512) {
        int ch = j / 36, lx = j - ch * 36;
        int ix = x0 - 2 + lx;
        bool vx = (ix >= 0 && ix < 224);
        const float* base = hr + ((long)(b * 256 + cb * 32 + ch) * 224) * 224 + ix;
        float w0 = 0.f, w1 = 0.f, w2 = 0.f, w3 = 0.f, w4 = 0.f;
        float* ov = s_v + ch * 593 + lx;
#pragma unroll
        for (int yy = 0; yy < 20; yy++) {
            int iy = y0 - 2 + yy;
            float v = (vx && iy >= 0 && iy < 224) ? base[iy * 224] : 0.f;
            w0 = w1; w1 = w2; w2 = w3; w3 = w4; w4 = v;
            if (yy >= 4) {
                float o = w0*tb[0] + w1*tb[1] + w2*tb[2] + w3*tb[3] + w4*tb[4];
                ov[(yy - 4) * 37] = o;
            }
        }
    }
    __syncthreads();

    // phase 2: horizontal blur + transposed store (lane = channel -> 128B stores)
    {
        int ch = t & 31, yr = t >> 5;   // yr 0..15
        const float* vp = s_v + ch * 593 + yr * 37;
        float* ob = g_blur + ((long)(b * 224 + y0 + yr) * 224 + x0) * 256 + cb * 32 + ch;
        float a0 = vp[0], a1 = vp[1], a2 = vp[2], a3 = vp[3];
#pragma unroll
        for (int x = 0; x < 32; x++) {
            float a4 = vp[x + 4];
            float o = a0*tb[0] + a1*tb[1] + a2*tb[2] + a3*tb[3] + a4*tb[4];
            ob[x * 256] = o;
            a0 = a1; a1 = a2; a2 = a3; a3 = a4;
        }
    }
}

// ---------------- fused logits + softmax + einsum v4 ----------------
// CTA: 2x8 output tile, 384 threads.
// s_blur: 5x17 region, parity-split rows, 85 rows x 260 floats:
//   even rix: row = riy*9 + rix/2      (45 rows)
//   odd  rix: row = 45 + riy*8 + rix/2 (40 rows)
// phase B thread tile: (cs = t&31 [8ch slice: c4=cs and cs+32],
//                       kg = (t>>5)%3 [3 k's], pg = t/96 [4 px: py=pg>>1, xh=pg&1])
//   acc[3][4] = 12 regs; per tap: 8 LDS.128 (v) + 6 LDG.128 (w) + 96 FMA.
//   Warp = (pg,kg); butterfly over 32 lanes reduces all 256 channels ->
//   lane 0 writes logits directly (no combine phase).
// smem floats: s_blur 22100 | s_logit 144 | s_attn 144
#define FUSED_SMEM ((22100 + 144 + 144) * 4)

__global__ void __launch_bounds__(384) fused_kernel(
    const void* __restrict__ maskp,
    const float* __restrict__ kbias,
    const float* __restrict__ lbias,
    float* __restrict__ out)
{
    extern __shared__ float sm[];
    float* s_blur  = sm;             // 22100
    float* s_logit = sm + 22100;     // 144
    float* s_attn  = sm + 22244;     // 144

    int t = threadIdx.x;
    int b = blockIdx.z;
    int x0o = blockIdx.x * 8, y0o = blockIdx.y * 2;
    int rx0 = 2 * x0o - 1, ry0 = 2 * y0o - 1;

    // ---- load 5x17 blurred region (85 rows x 256ch), 6 row-streams ----
    {
        int c4 = t & 63, rr = t >> 6;   // rr 0..5
        const float* gb = g_blur + (long)b * 224 * 224 * 256 + c4 * 4;
        for (int row = rr; row < 85; row += 6) {
            int riy, rix;
            if (row < 45) { riy = row / 9;  rix = 2 * (row - riy * 9); }
            else { int q = row - 45; riy = q >> 3; rix = 2 * (q & 7) + 1; }
            int iy = ry0 + riy, ix = rx0 + rix;
            float4 v = make_float4(0.f, 0.f, 0.f, 0.f);
            if (iy >= 0 && iy < 224 && ix >= 0 && ix < 224)
                v = *(const float4*)(gb + ((long)iy * 224 + ix) * 256);
            *(float4*)(s_blur + row * 260 + c4 * 4) = v;
        }
    }
    __syncthreads();

    // ---- phase B: logits, thread tile 4px x 3k x 8ch ----
    {
        int cs = t & 31;
        int kg = (t >> 5) % 3;
        int pg = t / 96;                 // 0..3
        int py = pg >> 1, xh = pg & 1;
        const float4* sb4 = (const float4*)s_blur;   // row stride 65 float4
        const float4* wp4 = (const float4*)g_wp;     // kt stride 64 float4

        float acc[3][4];
#pragma unroll
        for (int k = 0; k < 3; k++)
#pragma unroll
            for (int i = 0; i < 4; i++) acc[k][i] = 0.f;

#pragma unroll
        for (int dy = 0; dy < 3; dy++) {
            int riy = 2 * py + dy;
            int re = riy * 9 + 4 * xh;        // even-rix base (dx=0)
            int ro = 45 + riy * 8 + 4 * xh;   // odd-rix base
#pragma unroll
            for (int dx = 0; dx < 3; dx++) {
                int rbase = (dx == 1) ? ro : (re + (dx >> 1));
                int tap = dy * 3 + dx;
                float4 vl[4], vh[4];
#pragma unroll
                for (int i = 0; i < 4; i++) {
                    vl[i] = sb4[(rbase + i) * 65 + cs];
                    vh[i] = sb4[(rbase + i) * 65 + cs + 32];
                }
#pragma unroll
                for (int k = 0; k < 3; k++) {
                    int kt = (kg * 3 + k) * 9 + tap;
                    float4 wl = __ldg(&wp4[kt * 64 + cs]);
                    float4 wh = __ldg(&wp4[kt * 64 + cs + 32]);
#pragma unroll
                    for (int i = 0; i < 4; i++) {
                        float a = acc[k][i];
                        a = fmaf(vl[i].x, wl.x, a);
                        a = fmaf(vl[i].y, wl.y, a);
                        a = fmaf(vl[i].z, wl.z, a);
                        a = fmaf(vl[i].w, wl.w, a);
                        a = fmaf(vh[i].x, wh.x, a);
                        a = fmaf(vh[i].y, wh.y, a);
                        a = fmaf(vh[i].z, wh.z, a);
                        a = fmaf(vh[i].w, wh.w, a);
                        acc[k][i] = a;
                    }
                }
            }
        }

        // butterfly over 32 channel-slices = full 256-channel reduction
#pragma unroll
        for (int o = 16; o; o >>= 1)
#pragma unroll
            for (int k = 0; k < 3; k++)
#pragma unroll
                for (int i = 0; i < 4; i++)
                    acc[k][i] += __shfl_xor_sync(0xffffffffu, acc[k][i], o);

        if (cs == 0) {
#pragma unroll
            for (int k = 0; k < 3; k++)
#pragma unroll
                for (int i = 0; i < 4; i++) {
                    int p = py * 8 + 4 * xh + i;
                    s_logit[p * 9 + kg * 3 + k] = acc[k][i];
                }
        }
    }
    __syncthreads();

    // ---- softmax over 9 with kbias + keep_mask + logit_bias ----
    if (t < 16) {
        int p = t;
        int oy = y0o + (p >> 3), ox = x0o + (p & 7);
        int mm = g_mask_mode;
        float lg[9];
#pragma unroll
        for (int k = 0; k < 9; k++) {
            long midx = ((long)(b * 9 + k) * 112 + oy) * 112 + ox;
            bool keep;
            if (mm == 0)      keep = ((const unsigned char*)maskp)[midx] != 0;
            else if (mm == 1) keep = ((const int*)maskp)[midx] != 0;
            else              keep = ((const float*)maskp)[midx] != 0.f;
            lg[k] = (keep ? (s_logit[p * 9 + k] + kbias[k]) : 0.f) + lbias[k];
        }
        float mx = lg[0];
#pragma unroll
        for (int k = 1; k < 9; k++) mx = fmaxf(mx, lg[k]);
        float e[9]; float ssum = 0.f;
#pragma unroll
        for (int k = 0; k < 9; k++) { e[k] = expf(lg[k] - mx); ssum += e[k]; }
        float invs = 1.0f / ssum;
#pragma unroll
        for (int k = 0; k < 9; k++) s_attn[p * 9 + k] = e[k] * invs;
    }
    __syncthreads();

    // ---- einsum: thread = c (first 256 threads), both rows, 16 outputs ----
    if (t < 256) {
        int c = t;
#pragma unroll
        for (int r = 0; r < 2; r++) {
            float ox[8];
#pragma unroll
            for (int x = 0; x < 8; x++) ox[x] = 0.f;
#pragma unroll
            for (int dy = 0; dy < 3; dy++) {
                int riy = 2 * r + dy;
#pragma unroll
                for (int dx = 0; dx < 3; dx++) {
                    int k = dy * 3 + dx;
#pragma unroll
                    for (int x = 0; x < 8; x++) {
                        int rix = 2 * x + dx;
                        int row = (rix & 1) ? (45 + riy * 8 + (rix >> 1))
                                            : (riy * 9 + (rix >> 1));
                        float v = s_blur[row * 260 + c];
                        float a = s_attn[(r * 8 + x) * 9 + k];
                        ox[x] = fmaf(v, a, ox[x]);
                    }
                }
            }
            float* ob = out + ((long)(b * 256 + c) * 112 + y0o + r) * 112 + x0o;
            *(float4*)(ob)     = make_float4(ox[0], ox[1], ox[2], ox[3]);
            *(float4*)(ob + 4) = make_float4(ox[4], ox[5], ox[6], ox[7]);
        }
    }
}

// ---------------- launch ----------------
extern "C" void kernel_launch(void* const* d_in, const int* in_sizes, int n_in,
                              void* d_out, int out_size) {
    const float* hr  = (const float*)d_in[0];
    const float* ak  = (const float*)d_in[1];
    const float* kb  = (const float*)d_in[2];
    const float* lb  = (const float*)d_in[3];
    const void*  msk = d_in[4];
    float* out = (float*)d_out;
    (void)in_sizes; (void)n_in; (void)out_size;

    cudaFuncSetAttribute(blur_kernel,  cudaFuncAttributeMaxDynamicSharedMemorySize, BLUR_SMEM);
    cudaFuncSetAttribute(fused_kernel, cudaFuncAttributeMaxDynamicSharedMemorySize, FUSED_SMEM);

    detect_mask_kernel<<<1, 32>>>((const unsigned*)msk);
    repack_kernel<<<81, 256>>>(ak);
    blur_kernel<<<dim3(98, 8, 4), 512, BLUR_SMEM>>>(hr);
    fused_kernel<<<dim3(14, 56, 4), 384, FUSED_SMEM>>>(msk, kb, lb, out);
}